// round 15
// baseline (speedup 1.0000x reference)
#include <cuda_runtime.h>
#include <cuda_bf16.h>
#include <cstdint>

#define BB   32
#define CC   512
#define HW2  1024
#define NW   77
#define NP   80          // padded n
#define WD   256
#define MP   (BB * NP)   // 2560 padded rows

// ---------------- scratch ----------------
__device__ __nv_bfloat16 g_we_hi[(size_t)BB * NP * HW2];
__device__ __nv_bfloat16 g_we_lo[(size_t)BB * NP * HW2];

// ---------------- helpers ----------------
__device__ __forceinline__ uint32_t smem_to_u32(const void* p) {
    uint32_t a;
    asm("{ .reg .u64 t; cvta.to.shared.u64 t, %1; cvt.u32.u64 %0, t; }" : "=r"(a) : "l"(p));
    return a;
}
__device__ __forceinline__ void mma_bf16(float* c, const uint32_t* a, uint32_t b0, uint32_t b1) {
    asm volatile(
        "mma.sync.aligned.m16n8k16.row.col.f32.bf16.bf16.f32 "
        "{%0,%1,%2,%3}, {%4,%5,%6,%7}, {%8,%9}, {%0,%1,%2,%3};"
        : "+f"(c[0]), "+f"(c[1]), "+f"(c[2]), "+f"(c[3])
        : "r"(a[0]), "r"(a[1]), "r"(a[2]), "r"(a[3]), "r"(b0), "r"(b1));
}
__device__ __forceinline__ void ldsm4(uint32_t* r, uint32_t addr) {
    asm volatile("ldmatrix.sync.aligned.m8n8.x4.shared.b16 {%0,%1,%2,%3}, [%4];"
        : "=r"(r[0]), "=r"(r[1]), "=r"(r[2]), "=r"(r[3]) : "r"(addr));
}
__device__ __forceinline__ void ldsm4t(uint32_t* r, uint32_t addr) {
    asm volatile("ldmatrix.sync.aligned.m8n8.x4.trans.shared.b16 {%0,%1,%2,%3}, [%4];"
        : "=r"(r[0]), "=r"(r[1]), "=r"(r[2]), "=r"(r[3]) : "r"(addr));
}
__device__ __forceinline__ void split2(float v0, float v1, uint32_t& ph, uint32_t& pl) {
    __nv_bfloat16 h0 = __float2bfloat16(v0), h1 = __float2bfloat16(v1);
    float r0 = v0 - __bfloat162float(h0), r1 = v1 - __bfloat162float(h1);
    __nv_bfloat16 l0 = __float2bfloat16(r0), l1 = __float2bfloat16(r1);
    ph = (uint32_t)__bfloat16_as_ushort(h0) | ((uint32_t)__bfloat16_as_ushort(h1) << 16);
    pl = (uint32_t)__bfloat16_as_ushort(l0) | ((uint32_t)__bfloat16_as_ushort(l1) << 16);
}
#define CP16(dst, src) asm volatile("cp.async.cg.shared.global [%0], [%1], 16;" :: "r"(dst), "l"(src))
#define CP_COMMIT()    asm volatile("cp.async.commit_group;" ::: "memory")
#define CP_WAIT0()     asm volatile("cp.async.wait_group 0;" ::: "memory")
#define CP_WAIT1()     asm volatile("cp.async.wait_group 1;" ::: "memory")

#define SA  144

// ---------------------------------------------------------------------------
// Kernel 1: we = word_emb @ W_fc^T + b_fc, fp32 inputs split to bf16 hi/lo
// in registers (no separate split kernel). 64-row CTAs, 256 threads,
// 8 warps = 2 rowgroups(32r) x 4 colgroups(32c); K=256 in 4 chunks of 64,
// register-prefetch double-buffered stages.
// ---------------------------------------------------------------------------
#define G_AH 0
#define G_AL 9216
#define G_BH 18432
#define G_BL 36864
#define G_STAGE 55296
#define G_SMEM  110592

__global__ __launch_bounds__(256, 2) void we_gemm_tc(const float* __restrict__ we_in,
                                                     const float* __restrict__ Wfc,
                                                     const float* __restrict__ bfc) {
    extern __shared__ char smem[];
    const uint32_t sb = smem_to_u32(smem);
    const int tid  = threadIdx.x;
    const int wid  = tid >> 5;
    const int lane = tid & 31;
    const int q    = lane & 3;
    const int g    = lane >> 2;
    const int rg   = wid & 1;          // 2 rowgroups of 32
    const int cg   = wid >> 1;         // 4 colgroups of 32
    const int m0   = blockIdx.y * 64;
    const int k0   = blockIdx.x * 128;
    const int r0   = rg * 32;
    const int c0w  = cg * 32;

    float acc[2][4][4];
#pragma unroll
    for (int mt = 0; mt < 2; mt++)
#pragma unroll
        for (int t = 0; t < 4; t++)
#pragma unroll
            for (int j = 0; j < 4; j++) acc[mt][t][j] = 0.f;

    const int am = lane >> 3;
    const int ar = lane & 7;
    const uint32_t arow = (uint32_t)((am & 1) * 8 + ar) * SA + (uint32_t)(am >> 1) * 16;
    const uint32_t b4row = (uint32_t)((lane >> 4) * 8 + ar) * SA + (uint32_t)((lane >> 3) & 1) * 16;

    // loaders: A 64 rows x 64 cols fp32 (4 thr/row, 16 cols each);
    //          B 128 rows x 64 cols fp32 (2 thr/row, 32 cols each)
    const int lrA = tid >> 2, lhA = tid & 3;
    const int mpA = m0 + lrA;
    const int bbA = mpA / NP, nnA = mpA % NP;
    const bool a_valid = (nnA < NW);
    const float* asrc = we_in + ((size_t)bbA * NW + nnA) * WD + lhA * 16;
    const int lrB = tid >> 1, lhB = tid & 1;
    const float* bsrc = Wfc + (size_t)(k0 + lrB) * WD + lhB * 32;

    float4 pfA[4];
    float4 pfB[8];
    auto load_regs = [&](int ch) {
        const int dc = ch * 64;
#pragma unroll
        for (int i = 0; i < 4; i++)
            pfA[i] = a_valid ? *(const float4*)(asrc + dc + i * 4)
                             : make_float4(0.f, 0.f, 0.f, 0.f);
#pragma unroll
        for (int i = 0; i < 8; i++)
            pfB[i] = *(const float4*)(bsrc + dc + i * 4);
    };
    auto store_stage = [&](int s) {
        uint32_t h[16], l[16];
#pragma unroll
        for (int i = 0; i < 4; i++) {
            split2(pfA[i].x, pfA[i].y, h[2 * i], l[2 * i]);
            split2(pfA[i].z, pfA[i].w, h[2 * i + 1], l[2 * i + 1]);
        }
        uint4* ph_ = (uint4*)(smem + s * G_STAGE + G_AH + lrA * SA + lhA * 32);
        uint4* pl_ = (uint4*)(smem + s * G_STAGE + G_AL + lrA * SA + lhA * 32);
        ph_[0] = make_uint4(h[0], h[1], h[2], h[3]);
        ph_[1] = make_uint4(h[4], h[5], h[6], h[7]);
        pl_[0] = make_uint4(l[0], l[1], l[2], l[3]);
        pl_[1] = make_uint4(l[4], l[5], l[6], l[7]);
#pragma unroll
        for (int i = 0; i < 8; i++) {
            split2(pfB[i].x, pfB[i].y, h[2 * i], l[2 * i]);
            split2(pfB[i].z, pfB[i].w, h[2 * i + 1], l[2 * i + 1]);
        }
        uint4* qh_ = (uint4*)(smem + s * G_STAGE + G_BH + lrB * SA + lhB * 64);
        uint4* ql_ = (uint4*)(smem + s * G_STAGE + G_BL + lrB * SA + lhB * 64);
#pragma unroll
        for (int i = 0; i < 4; i++) {
            qh_[i] = make_uint4(h[4 * i], h[4 * i + 1], h[4 * i + 2], h[4 * i + 3]);
            ql_[i] = make_uint4(l[4 * i], l[4 * i + 1], l[4 * i + 2], l[4 * i + 3]);
        }
    };

    load_regs(0);
    store_stage(0);

    for (int ch = 0; ch < 4; ch++) {
        const int s = ch & 1;
        if (ch < 3) load_regs(ch + 1);
        __syncthreads();

        const uint32_t st = sb + (uint32_t)s * G_STAGE;
#pragma unroll
        for (int ks = 0; ks < 4; ks++) {
            const uint32_t kb = (uint32_t)ks * 32;
            uint32_t a_h[2][4], a_l[2][4];
#pragma unroll
            for (int mt = 0; mt < 2; mt++) {
                uint32_t ao = (uint32_t)(r0 + mt * 16) * SA + arow + kb;
                ldsm4(a_h[mt], st + G_AH + ao);
                ldsm4(a_l[mt], st + G_AL + ao);
            }
#pragma unroll
            for (int tp = 0; tp < 2; tp++) {
                uint32_t bo = (uint32_t)(c0w + tp * 16) * SA + b4row + kb;
                uint32_t b_h[4], b_l[4];
                ldsm4(b_h, st + G_BH + bo);
                ldsm4(b_l, st + G_BL + bo);
#pragma unroll
                for (int mt = 0; mt < 2; mt++) {
                    mma_bf16(acc[mt][2 * tp],     a_h[mt], b_h[0], b_h[1]);
                    mma_bf16(acc[mt][2 * tp],     a_h[mt], b_l[0], b_l[1]);
                    mma_bf16(acc[mt][2 * tp],     a_l[mt], b_h[0], b_h[1]);
                    mma_bf16(acc[mt][2 * tp + 1], a_h[mt], b_h[2], b_h[3]);
                    mma_bf16(acc[mt][2 * tp + 1], a_h[mt], b_l[2], b_l[3]);
                    mma_bf16(acc[mt][2 * tp + 1], a_l[mt], b_h[2], b_h[3]);
                }
            }
        }
        if (ch < 3) store_stage(s ^ 1);
        __syncthreads();
    }

    // epilogue: bias, zero padded rows, split to bf16 hi/lo
#pragma unroll
    for (int mt = 0; mt < 2; mt++) {
        const int mp0 = m0 + r0 + mt * 16 + g;
        const int mp1 = mp0 + 8;
        const bool v0ok = ((mp0 % NP) < NW);
        const bool v1ok = ((mp1 % NP) < NW);
#pragma unroll
        for (int t = 0; t < 4; t++) {
            const int col = k0 + c0w + t * 8 + 2 * q;
            const float b0 = bfc[col], b1 = bfc[col + 1];
            float v00 = v0ok ? acc[mt][t][0] + b0 : 0.f;
            float v01 = v0ok ? acc[mt][t][1] + b1 : 0.f;
            float v10 = v1ok ? acc[mt][t][2] + b0 : 0.f;
            float v11 = v1ok ? acc[mt][t][3] + b1 : 0.f;
            uint32_t ph, pl;
            split2(v00, v01, ph, pl);
            *(uint32_t*)(g_we_hi + (size_t)mp0 * HW2 + col) = ph;
            *(uint32_t*)(g_we_lo + (size_t)mp0 * HW2 + col) = pl;
            split2(v10, v11, ph, pl);
            *(uint32_t*)(g_we_hi + (size_t)mp1 * HW2 + col) = ph;
            *(uint32_t*)(g_we_lo + (size_t)mp1 * HW2 + col) = pl;
        }
    }
}

// ---------------------------------------------------------------------------
// Kernel 2: fused attention (unchanged from R14 — 64-row CTAs, 256 threads)
// ---------------------------------------------------------------------------
#define P1_AH 0
#define P1_AL 9216
#define P1_BH 18432
#define P1_BL 29952
#define P1_STAGE 41472
#define SCR0_OFF 0
#define SCR1_OFF 20736
#define SCR_S    81
#define WS_A     43520
#define WS_B     0
#define W_PITCH  272
#define W_HL     21760
#define ATTH_OFF 87040
#define ATTL_OFF 98304
#define ATT_S    44
#define SMEM_ATT 109568

__global__ __launch_bounds__(256, 2) void attn_tc(const float* __restrict__ feat,
                                                  float* __restrict__ out) {
    extern __shared__ char smem[];
    const uint32_t sb = smem_to_u32(smem);
    const int tid  = threadIdx.x;
    const int wid  = tid >> 5;
    const int lane = tid & 31;
    const int q    = lane & 3;
    const int g    = lane >> 2;
    const int b    = blockIdx.y;
    const int c0   = blockIdx.x * 64;

    const int rg1 = wid & 1;
    const int cg1 = (wid >> 1) & 1;
    const int kh1 = wid >> 2;
    const int r01 = rg1 * 32;
    const int c0w = cg1 * 40;

    const float* fb = feat + ((size_t)b * CC + c0) * HW2;
    const __nv_bfloat16* weh = g_we_hi + (size_t)b * NP * HW2;
    const __nv_bfloat16* wel = g_we_lo + (size_t)b * NP * HW2;

    const int ar = lane & 7;
    const int lb3 = (lane >> 3) & 1;
    const int lb4 = lane >> 4;
    const int am = lane >> 3;
    const uint32_t arow = (uint32_t)((am & 1) * 8 + ar) * SA + (uint32_t)(am >> 1) * 16;
    const uint32_t b4row = (uint32_t)(lb4 * 8 + ar) * SA + (uint32_t)lb3 * 16;
    const uint32_t cmb_base = (uint32_t)((lane < 16) ? P1_BH : P1_BL) +
                              (uint32_t)(c0w + 32 + ar) * SA +
                              (uint32_t)lb3 * 16;

    const int lr = tid >> 2, lh = tid & 3;
    auto load_A_regs = [&](int ch, float4* pf) {
        const float* src = fb + (size_t)lr * HW2 + ch * 64 + lh * 16;
#pragma unroll
        for (int i = 0; i < 4; i++) pf[i] = *(const float4*)(src + i * 4);
    };
    auto store_A = [&](int s, const float4* pf) {
        uint32_t h[8], l[8];
#pragma unroll
        for (int i = 0; i < 4; i++) {
            split2(pf[i].x, pf[i].y, h[2 * i], l[2 * i]);
            split2(pf[i].z, pf[i].w, h[2 * i + 1], l[2 * i + 1]);
        }
        uint4* ph_ = (uint4*)(smem + s * P1_STAGE + P1_AH + lr * SA + lh * 32);
        uint4* pl_ = (uint4*)(smem + s * P1_STAGE + P1_AL + lr * SA + lh * 32);
        ph_[0] = make_uint4(h[0], h[1], h[2], h[3]);
        ph_[1] = make_uint4(h[4], h[5], h[6], h[7]);
        pl_[0] = make_uint4(l[0], l[1], l[2], l[3]);
        pl_[1] = make_uint4(l[4], l[5], l[6], l[7]);
    };
    auto load_B = [&](int ch, int s) {
        const int kc = ch * 64;
        const uint32_t st = sb + (uint32_t)s * P1_STAGE;
        for (int i = tid; i < 640; i += 256) {
            int r = i >> 3, cch = i & 7;
            uint32_t off = (uint32_t)r * SA + (uint32_t)cch * 16;
            CP16(st + P1_BH + off, weh + (size_t)r * HW2 + kc + cch * 8);
            CP16(st + P1_BL + off, wel + (size_t)r * HW2 + kc + cch * 8);
        }
    };

    float acc[2][5][4];
#pragma unroll
    for (int mt = 0; mt < 2; mt++)
#pragma unroll
        for (int t = 0; t < 5; t++)
#pragma unroll
            for (int j = 0; j < 4; j++) acc[mt][t][j] = 0.f;

    float4 pf[4];
    load_A_regs(0, pf);
    load_B(0, 0);
    CP_COMMIT();
    store_A(0, pf);

    for (int it = 0; it < 16; it++) {
        const int s = it & 1;
        if (it < 15) {
            load_A_regs(it + 1, pf);
            load_B(it + 1, s ^ 1);
            CP_COMMIT();
        }
        if (it < 15) CP_WAIT1(); else CP_WAIT0();
        __syncthreads();

        const uint32_t st = sb + (uint32_t)s * P1_STAGE;
#pragma unroll
        for (int ks = 0; ks < 2; ks++) {
            const uint32_t kb = (uint32_t)(kh1 * 64 + ks * 32);
            uint32_t a_h[2][4], a_l[2][4];
#pragma unroll
            for (int mt = 0; mt < 2; mt++) {
                uint32_t ao = (uint32_t)(r01 + mt * 16) * SA + arow + kb;
                ldsm4(a_h[mt], st + P1_AH + ao);
                ldsm4(a_l[mt], st + P1_AL + ao);
            }
            uint32_t b_h[2][4], b_l[2][4], bc[4];
#pragma unroll
            for (int tp = 0; tp < 2; tp++) {
                uint32_t bo = (uint32_t)(c0w + tp * 16) * SA + b4row + kb;
                ldsm4(b_h[tp], st + P1_BH + bo);
                ldsm4(b_l[tp], st + P1_BL + bo);
            }
            ldsm4(bc, st + cmb_base + kb);
#pragma unroll
            for (int mt = 0; mt < 2; mt++) {
#pragma unroll
                for (int tp = 0; tp < 2; tp++) {
                    mma_bf16(acc[mt][2 * tp],     a_h[mt], b_h[tp][0], b_h[tp][1]);
                    mma_bf16(acc[mt][2 * tp],     a_h[mt], b_l[tp][0], b_l[tp][1]);
                    mma_bf16(acc[mt][2 * tp],     a_l[mt], b_h[tp][0], b_h[tp][1]);
                    mma_bf16(acc[mt][2 * tp + 1], a_h[mt], b_h[tp][2], b_h[tp][3]);
                    mma_bf16(acc[mt][2 * tp + 1], a_h[mt], b_l[tp][2], b_l[tp][3]);
                    mma_bf16(acc[mt][2 * tp + 1], a_l[mt], b_h[tp][2], b_h[tp][3]);
                }
                mma_bf16(acc[mt][4], a_h[mt], bc[0], bc[1]);
                mma_bf16(acc[mt][4], a_h[mt], bc[2], bc[3]);
                mma_bf16(acc[mt][4], a_l[mt], bc[0], bc[1]);
            }
        }
        if (it < 15) store_A(s ^ 1, pf);
        __syncthreads();
    }

    float* myscr = (float*)(smem + (kh1 ? SCR1_OFF : SCR0_OFF));
#pragma unroll
    for (int mt = 0; mt < 2; mt++) {
        const int row0 = r01 + mt * 16 + g;
#pragma unroll
        for (int t = 0; t < 5; t++) {
            const int col = c0w + t * 8 + 2 * q;
            myscr[row0 * SCR_S + col]       = acc[mt][t][0];
            myscr[row0 * SCR_S + col + 1]   = acc[mt][t][1];
            myscr[(row0 + 8) * SCR_S + col]     = acc[mt][t][2];
            myscr[(row0 + 8) * SCR_S + col + 1] = acc[mt][t][3];
        }
    }
    __syncthreads();

    auto load_W = [&](int oc, uint32_t ws) {
        const int k0 = oc * 128;
        for (int i = tid; i < 1280; i += 256) {
            int r = i >> 4, c = i & 15;
            uint32_t off = (uint32_t)r * W_PITCH + (uint32_t)c * 16;
            CP16(sb + ws + off, weh + (size_t)r * HW2 + k0 + c * 8);
            CP16(sb + ws + W_HL + off, wel + (size_t)r * HW2 + k0 + c * 8);
        }
    };
    load_W(0, WS_A);
    CP_COMMIT();

    uint32_t* atth = (uint32_t*)(smem + ATTH_OFF);
    uint32_t* attl = (uint32_t*)(smem + ATTL_OFF);
    {
        const int row = tid >> 2, t4 = tid & 3;
        float* r0p = (float*)(smem + SCR0_OFF) + row * SCR_S;
        float* r1p = (float*)(smem + SCR1_OFF) + row * SCR_S;
        float vals[20];
        const int n0 = t4 * 20;
        const int n1 = (n0 + 20 < NW) ? n0 + 20 : NW;
        float mx = -1e30f;
        for (int n = n0; n < n1; n++) {
            float v = r0p[n] + r1p[n];
            vals[n - n0] = v;
            mx = fmaxf(mx, v);
        }
        mx = fmaxf(mx, __shfl_xor_sync(0xffffffffu, mx, 1));
        mx = fmaxf(mx, __shfl_xor_sync(0xffffffffu, mx, 2));
        float s = 0.f;
        for (int n = n0; n < n1; n++) {
            float e = __expf(vals[n - n0] - mx);
            vals[n - n0] = e;
            s += e;
        }
        s += __shfl_xor_sync(0xffffffffu, s, 1);
        s += __shfl_xor_sync(0xffffffffu, s, 2);
        const float inv = 1.f / s;
#pragma unroll
        for (int p = 0; p < 10; p++) {
            const int pp = t4 * 10 + p;
            float v0 = (2 * pp < n1 && 2 * pp >= n0)         ? vals[2 * pp - n0] * inv     : 0.f;
            float v1 = (2 * pp + 1 < n1 && 2 * pp + 1 >= n0) ? vals[2 * pp + 1 - n0] * inv : 0.f;
            uint32_t ph, pl;
            split2(v0, v1, ph, pl);
            atth[row * ATT_S + pp] = ph;
            attl[row * ATT_S + pp] = pl;
        }
    }
    __syncthreads();

    const int rg3 = wid & 1;
    const int cg3 = wid >> 1;
    const int r03 = rg3 * 32;
    const int c0w3 = cg3 * 32;

    for (int oc = 0; oc < 8; oc++) {
        const uint32_t ws = (oc & 1) ? WS_B : WS_A;
        if (oc < 7) { load_W(oc + 1, (oc & 1) ? WS_A : WS_B); CP_COMMIT(); }
        if (oc < 7) CP_WAIT1(); else CP_WAIT0();
        __syncthreads();

        float acc2[2][4][4];
#pragma unroll
        for (int mt = 0; mt < 2; mt++)
#pragma unroll
            for (int t = 0; t < 4; t++)
#pragma unroll
                for (int j = 0; j < 4; j++) acc2[mt][t][j] = 0.f;

#pragma unroll
        for (int ks = 0; ks < 5; ks++) {
            uint32_t a_h[2][4], a_l[2][4];
#pragma unroll
            for (int mt = 0; mt < 2; mt++) {
                uint32_t aoff = ((uint32_t)(r03 + mt * 16 + ar + lb3 * 8) * ATT_S +
                                 (uint32_t)(ks * 8 + lb4 * 4)) * 4;
                ldsm4(a_h[mt], sb + ATTH_OFF + aoff);
                ldsm4(a_l[mt], sb + ATTL_OFF + aoff);
            }
#pragma unroll
            for (int tp = 0; tp < 2; tp++) {
                uint32_t woff = (uint32_t)(ks * 16 + ar + lb3 * 8) * W_PITCH +
                                (uint32_t)(c0w3 + tp * 16 + lb4 * 8) * 2;
                uint32_t b_h[4], b_l[4];
                ldsm4t(b_h, sb + ws + woff);
                ldsm4t(b_l, sb + ws + W_HL + woff);
#pragma unroll
                for (int mt = 0; mt < 2; mt++) {
                    mma_bf16(acc2[mt][2 * tp],     a_h[mt], b_h[0], b_h[1]);
                    mma_bf16(acc2[mt][2 * tp],     a_h[mt], b_l[0], b_l[1]);
                    mma_bf16(acc2[mt][2 * tp],     a_l[mt], b_h[0], b_h[1]);
                    mma_bf16(acc2[mt][2 * tp + 1], a_h[mt], b_h[2], b_h[3]);
                    mma_bf16(acc2[mt][2 * tp + 1], a_h[mt], b_l[2], b_l[3]);
                    mma_bf16(acc2[mt][2 * tp + 1], a_l[mt], b_h[2], b_h[3]);
                }
            }
        }

        const int k0 = oc * 128;
#pragma unroll
        for (int mt = 0; mt < 2; mt++) {
            float* ob = out + ((size_t)b * CC + c0 + r03 + mt * 16) * HW2 + k0 + c0w3;
#pragma unroll
            for (int t = 0; t < 4; t++) {
                int col = t * 8 + 2 * q;
                *(float2*)&ob[(size_t)g * HW2 + col]       = make_float2(acc2[mt][t][0], acc2[mt][t][1]);
                *(float2*)&ob[(size_t)(g + 8) * HW2 + col] = make_float2(acc2[mt][t][2], acc2[mt][t][3]);
            }
        }
        __syncthreads();
    }
}

// ---------------------------------------------------------------------------
extern "C" void kernel_launch(void* const* d_in, const int* in_sizes, int n_in,
                              void* d_out, int out_size) {
    const float* feat     = (const float*)d_in[0];
    const float* word_emb = (const float*)d_in[1];
    const float* W_fc     = (const float*)d_in[2];
    const float* b_fc     = (const float*)d_in[3];
    float* out            = (float*)d_out;
    (void)in_sizes; (void)n_in; (void)out_size;

    cudaFuncSetAttribute(we_gemm_tc, cudaFuncAttributeMaxDynamicSharedMemorySize, G_SMEM);
    cudaFuncSetAttribute(attn_tc, cudaFuncAttributeMaxDynamicSharedMemorySize, SMEM_ATT);

    we_gemm_tc<<<dim3(HW2 / 128, MP / 64), 256, G_SMEM>>>(word_emb, W_fc, b_fc); // (8, 40)
    attn_tc<<<dim3(CC / 64, BB), 256, SMEM_ATT>>>(feat, out);                    // (8, 32)
}

// round 16
// speedup vs baseline: 1.1734x; 1.1734x over previous
#include <cuda_runtime.h>
#include <cuda_bf16.h>
#include <cstdint>

#define BB   32
#define CC   512
#define HW2  1024
#define NW   77
#define NP   80          // padded n
#define WD   256
#define MP   (BB * NP)   // 2560 padded rows

// ---------------- scratch ----------------
__device__ __nv_bfloat16 g_a_hi[(size_t)MP * WD];
__device__ __nv_bfloat16 g_a_lo[(size_t)MP * WD];
__device__ __nv_bfloat16 g_w_hi[(size_t)HW2 * WD];
__device__ __nv_bfloat16 g_w_lo[(size_t)HW2 * WD];
__device__ __nv_bfloat16 g_we_hi[(size_t)BB * NP * HW2];
__device__ __nv_bfloat16 g_we_lo[(size_t)BB * NP * HW2];

// ---------------- helpers ----------------
__device__ __forceinline__ uint32_t smem_to_u32(const void* p) {
    uint32_t a;
    asm("{ .reg .u64 t; cvta.to.shared.u64 t, %1; cvt.u32.u64 %0, t; }" : "=r"(a) : "l"(p));
    return a;
}
__device__ __forceinline__ void mma_bf16(float* c, const uint32_t* a, uint32_t b0, uint32_t b1) {
    asm volatile(
        "mma.sync.aligned.m16n8k16.row.col.f32.bf16.bf16.f32 "
        "{%0,%1,%2,%3}, {%4,%5,%6,%7}, {%8,%9}, {%0,%1,%2,%3};"
        : "+f"(c[0]), "+f"(c[1]), "+f"(c[2]), "+f"(c[3])
        : "r"(a[0]), "r"(a[1]), "r"(a[2]), "r"(a[3]), "r"(b0), "r"(b1));
}
__device__ __forceinline__ void ldsm4(uint32_t* r, uint32_t addr) {
    asm volatile("ldmatrix.sync.aligned.m8n8.x4.shared.b16 {%0,%1,%2,%3}, [%4];"
        : "=r"(r[0]), "=r"(r[1]), "=r"(r[2]), "=r"(r[3]) : "r"(addr));
}
__device__ __forceinline__ void ldsm4t(uint32_t* r, uint32_t addr) {
    asm volatile("ldmatrix.sync.aligned.m8n8.x4.trans.shared.b16 {%0,%1,%2,%3}, [%4];"
        : "=r"(r[0]), "=r"(r[1]), "=r"(r[2]), "=r"(r[3]) : "r"(addr));
}
__device__ __forceinline__ void split2(float v0, float v1, uint32_t& ph, uint32_t& pl) {
    __nv_bfloat16 h0 = __float2bfloat16(v0), h1 = __float2bfloat16(v1);
    float r0 = v0 - __bfloat162float(h0), r1 = v1 - __bfloat162float(h1);
    __nv_bfloat16 l0 = __float2bfloat16(r0), l1 = __float2bfloat16(r1);
    ph = (uint32_t)__bfloat16_as_ushort(h0) | ((uint32_t)__bfloat16_as_ushort(h1) << 16);
    pl = (uint32_t)__bfloat16_as_ushort(l0) | ((uint32_t)__bfloat16_as_ushort(l1) << 16);
}
#define CP16(dst, src) asm volatile("cp.async.cg.shared.global [%0], [%1], 16;" :: "r"(dst), "l"(src))
#define CP_COMMIT()    asm volatile("cp.async.commit_group;" ::: "memory")
#define CP_WAIT0()     asm volatile("cp.async.wait_group 0;" ::: "memory")
#define CP_WAIT1()     asm volatile("cp.async.wait_group 1;" ::: "memory")

#define SA  144

// ---------------------------------------------------------------------------
// Kernel 0: elementwise bf16 hi/lo split of word_emb (padded) + W_fc
// ---------------------------------------------------------------------------
#define A_TASKS (MP * WD / 4)
#define W_TASKS (HW2 * WD / 4)
__global__ void split_inputs(const float* __restrict__ we_in,
                             const float* __restrict__ Wfc) {
    int idx = blockIdx.x * 256 + threadIdx.x;
    if (idx < A_TASKS) {
        int mp = idx >> 6, c4 = idx & 63;
        int bb = mp / NP, nn = mp % NP;
        float4 v = make_float4(0.f, 0.f, 0.f, 0.f);
        if (nn < NW) v = *(const float4*)(we_in + ((size_t)bb * NW + nn) * WD + c4 * 4);
        uint32_t h0, l0, h1, l1;
        split2(v.x, v.y, h0, l0);
        split2(v.z, v.w, h1, l1);
        *(uint2*)(g_a_hi + (size_t)mp * WD + c4 * 4) = make_uint2(h0, h1);
        *(uint2*)(g_a_lo + (size_t)mp * WD + c4 * 4) = make_uint2(l0, l1);
    } else if (idx < A_TASKS + W_TASKS) {
        int j = idx - A_TASKS;
        int r = j >> 6, c4 = j & 63;
        float4 v = *(const float4*)(Wfc + (size_t)r * WD + c4 * 4);
        uint32_t h0, l0, h1, l1;
        split2(v.x, v.y, h0, l0);
        split2(v.z, v.w, h1, l1);
        *(uint2*)(g_w_hi + (size_t)r * WD + c4 * 4) = make_uint2(h0, h1);
        *(uint2*)(g_w_lo + (size_t)r * WD + c4 * 4) = make_uint2(l0, l1);
    }
}

// ---------------------------------------------------------------------------
// Kernel 1: we = word_emb @ W_fc^T + b_fc (bf16 GEMM, cp.async 2-stage)
// 64-row CTAs, 256 threads, 8 warps = 2 rowgroups(32r) x 4 colgroups(32c).
// ---------------------------------------------------------------------------
#define G_AH 0
#define G_AL 9216
#define G_BH 18432
#define G_BL 36864
#define G_STAGE 55296
#define G_SMEM  110592

__global__ __launch_bounds__(256, 2) void we_gemm_tc(const float* __restrict__ bfc) {
    extern __shared__ char smem[];
    const uint32_t sb = smem_to_u32(smem);
    const int tid  = threadIdx.x;
    const int wid  = tid >> 5;
    const int lane = tid & 31;
    const int q    = lane & 3;
    const int g    = lane >> 2;
    const int rg   = wid & 1;          // 2 rowgroups of 32
    const int cg   = wid >> 1;         // 4 colgroups of 32
    const int m0   = blockIdx.y * 64;
    const int k0   = blockIdx.x * 128;
    const int r0   = rg * 32;
    const int c0w  = cg * 32;

    float acc[2][4][4];
#pragma unroll
    for (int mt = 0; mt < 2; mt++)
#pragma unroll
        for (int t = 0; t < 4; t++)
#pragma unroll
            for (int j = 0; j < 4; j++) acc[mt][t][j] = 0.f;

    const int am = lane >> 3;
    const int ar = lane & 7;
    const uint32_t arow = (uint32_t)((am & 1) * 8 + ar) * SA + (uint32_t)(am >> 1) * 16;
    const uint32_t b4row = (uint32_t)((lane >> 4) * 8 + ar) * SA + (uint32_t)((lane >> 3) & 1) * 16;

    auto load_chunk = [&](int ch, int s) {
        const int kc = ch * 64;
        const uint32_t st = sb + (uint32_t)s * G_STAGE;
        for (int i = tid; i < 1024; i += 256) {
            int r = i >> 3, c = i & 7;
            uint32_t off = (uint32_t)r * SA + (uint32_t)c * 16;
            CP16(st + G_BH + off, g_w_hi + (size_t)(k0 + r) * WD + kc + c * 8);
            CP16(st + G_BL + off, g_w_lo + (size_t)(k0 + r) * WD + kc + c * 8);
            if (r < 64) {
                CP16(st + G_AH + off, g_a_hi + (size_t)(m0 + r) * WD + kc + c * 8);
                CP16(st + G_AL + off, g_a_lo + (size_t)(m0 + r) * WD + kc + c * 8);
            }
        }
    };

    load_chunk(0, 0);
    CP_COMMIT();

    for (int ch = 0; ch < 4; ch++) {
        const int s = ch & 1;
        if (ch < 3) { load_chunk(ch + 1, s ^ 1); CP_COMMIT(); }
        if (ch < 3) CP_WAIT1(); else CP_WAIT0();
        __syncthreads();

        const uint32_t st = sb + (uint32_t)s * G_STAGE;
#pragma unroll
        for (int ks = 0; ks < 4; ks++) {
            const uint32_t kb = (uint32_t)ks * 32;
            uint32_t a_h[2][4], a_l[2][4];
#pragma unroll
            for (int mt = 0; mt < 2; mt++) {
                uint32_t ao = (uint32_t)(r0 + mt * 16) * SA + arow + kb;
                ldsm4(a_h[mt], st + G_AH + ao);
                ldsm4(a_l[mt], st + G_AL + ao);
            }
#pragma unroll
            for (int tp = 0; tp < 2; tp++) {
                uint32_t bo = (uint32_t)(c0w + tp * 16) * SA + b4row + kb;
                uint32_t b_h[4], b_l[4];
                ldsm4(b_h, st + G_BH + bo);
                ldsm4(b_l, st + G_BL + bo);
#pragma unroll
                for (int mt = 0; mt < 2; mt++) {
                    mma_bf16(acc[mt][2 * tp],     a_h[mt], b_h[0], b_h[1]);
                    mma_bf16(acc[mt][2 * tp],     a_h[mt], b_l[0], b_l[1]);
                    mma_bf16(acc[mt][2 * tp],     a_l[mt], b_h[0], b_h[1]);
                    mma_bf16(acc[mt][2 * tp + 1], a_h[mt], b_h[2], b_h[3]);
                    mma_bf16(acc[mt][2 * tp + 1], a_h[mt], b_l[2], b_l[3]);
                    mma_bf16(acc[mt][2 * tp + 1], a_l[mt], b_h[2], b_h[3]);
                }
            }
        }
        __syncthreads();
    }

    // epilogue
#pragma unroll
    for (int mt = 0; mt < 2; mt++) {
        const int mp0 = m0 + r0 + mt * 16 + g;
        const int mp1 = mp0 + 8;
        const bool v0ok = ((mp0 % NP) < NW);
        const bool v1ok = ((mp1 % NP) < NW);
#pragma unroll
        for (int t = 0; t < 4; t++) {
            const int col = k0 + c0w + t * 8 + 2 * q;
            const float b0 = bfc[col], b1 = bfc[col + 1];
            float v00 = v0ok ? acc[mt][t][0] + b0 : 0.f;
            float v01 = v0ok ? acc[mt][t][1] + b1 : 0.f;
            float v10 = v1ok ? acc[mt][t][2] + b0 : 0.f;
            float v11 = v1ok ? acc[mt][t][3] + b1 : 0.f;
            uint32_t ph, pl;
            split2(v00, v01, ph, pl);
            *(uint32_t*)(g_we_hi + (size_t)mp0 * HW2 + col) = ph;
            *(uint32_t*)(g_we_lo + (size_t)mp0 * HW2 + col) = pl;
            split2(v10, v11, ph, pl);
            *(uint32_t*)(g_we_hi + (size_t)mp1 * HW2 + col) = ph;
            *(uint32_t*)(g_we_lo + (size_t)mp1 * HW2 + col) = pl;
        }
    }
}

// ---------------------------------------------------------------------------
// Kernel 2: fused attention (identical to the 94.9us R14 version)
// ---------------------------------------------------------------------------
#define P1_AH 0
#define P1_AL 9216
#define P1_BH 18432
#define P1_BL 29952
#define P1_STAGE 41472
#define SCR0_OFF 0
#define SCR1_OFF 20736
#define SCR_S    81
#define WS_A     43520
#define WS_B     0
#define W_PITCH  272
#define W_HL     21760
#define ATTH_OFF 87040
#define ATTL_OFF 98304
#define ATT_S    44
#define SMEM_ATT 109568

__global__ __launch_bounds__(256, 2) void attn_tc(const float* __restrict__ feat,
                                                  float* __restrict__ out) {
    extern __shared__ char smem[];
    const uint32_t sb = smem_to_u32(smem);
    const int tid  = threadIdx.x;
    const int wid  = tid >> 5;
    const int lane = tid & 31;
    const int q    = lane & 3;
    const int g    = lane >> 2;
    const int b    = blockIdx.y;
    const int c0   = blockIdx.x * 64;

    const int rg1 = wid & 1;
    const int cg1 = (wid >> 1) & 1;
    const int kh1 = wid >> 2;
    const int r01 = rg1 * 32;
    const int c0w = cg1 * 40;

    const float* fb = feat + ((size_t)b * CC + c0) * HW2;
    const __nv_bfloat16* weh = g_we_hi + (size_t)b * NP * HW2;
    const __nv_bfloat16* wel = g_we_lo + (size_t)b * NP * HW2;

    const int ar = lane & 7;
    const int lb3 = (lane >> 3) & 1;
    const int lb4 = lane >> 4;
    const int am = lane >> 3;
    const uint32_t arow = (uint32_t)((am & 1) * 8 + ar) * SA + (uint32_t)(am >> 1) * 16;
    const uint32_t b4row = (uint32_t)(lb4 * 8 + ar) * SA + (uint32_t)lb3 * 16;
    const uint32_t cmb_base = (uint32_t)((lane < 16) ? P1_BH : P1_BL) +
                              (uint32_t)(c0w + 32 + ar) * SA +
                              (uint32_t)lb3 * 16;

    const int lr = tid >> 2, lh = tid & 3;
    auto load_A_regs = [&](int ch, float4* pf) {
        const float* src = fb + (size_t)lr * HW2 + ch * 64 + lh * 16;
#pragma unroll
        for (int i = 0; i < 4; i++) pf[i] = *(const float4*)(src + i * 4);
    };
    auto store_A = [&](int s, const float4* pf) {
        uint32_t h[8], l[8];
#pragma unroll
        for (int i = 0; i < 4; i++) {
            split2(pf[i].x, pf[i].y, h[2 * i], l[2 * i]);
            split2(pf[i].z, pf[i].w, h[2 * i + 1], l[2 * i + 1]);
        }
        uint4* ph_ = (uint4*)(smem + s * P1_STAGE + P1_AH + lr * SA + lh * 32);
        uint4* pl_ = (uint4*)(smem + s * P1_STAGE + P1_AL + lr * SA + lh * 32);
        ph_[0] = make_uint4(h[0], h[1], h[2], h[3]);
        ph_[1] = make_uint4(h[4], h[5], h[6], h[7]);
        pl_[0] = make_uint4(l[0], l[1], l[2], l[3]);
        pl_[1] = make_uint4(l[4], l[5], l[6], l[7]);
    };
    auto load_B = [&](int ch, int s) {
        const int kc = ch * 64;
        const uint32_t st = sb + (uint32_t)s * P1_STAGE;
        for (int i = tid; i < 640; i += 256) {
            int r = i >> 3, cch = i & 7;
            uint32_t off = (uint32_t)r * SA + (uint32_t)cch * 16;
            CP16(st + P1_BH + off, weh + (size_t)r * HW2 + kc + cch * 8);
            CP16(st + P1_BL + off, wel + (size_t)r * HW2 + kc + cch * 8);
        }
    };

    float acc[2][5][4];
#pragma unroll
    for (int mt = 0; mt < 2; mt++)
#pragma unroll
        for (int t = 0; t < 5; t++)
#pragma unroll
            for (int j = 0; j < 4; j++) acc[mt][t][j] = 0.f;

    float4 pf[4];
    load_A_regs(0, pf);
    load_B(0, 0);
    CP_COMMIT();
    store_A(0, pf);

    for (int it = 0; it < 16; it++) {
        const int s = it & 1;
        if (it < 15) {
            load_A_regs(it + 1, pf);
            load_B(it + 1, s ^ 1);
            CP_COMMIT();
        }
        if (it < 15) CP_WAIT1(); else CP_WAIT0();
        __syncthreads();

        const uint32_t st = sb + (uint32_t)s * P1_STAGE;
#pragma unroll
        for (int ks = 0; ks < 2; ks++) {
            const uint32_t kb = (uint32_t)(kh1 * 64 + ks * 32);
            uint32_t a_h[2][4], a_l[2][4];
#pragma unroll
            for (int mt = 0; mt < 2; mt++) {
                uint32_t ao = (uint32_t)(r01 + mt * 16) * SA + arow + kb;
                ldsm4(a_h[mt], st + P1_AH + ao);
                ldsm4(a_l[mt], st + P1_AL + ao);
            }
            uint32_t b_h[2][4], b_l[2][4], bc[4];
#pragma unroll
            for (int tp = 0; tp < 2; tp++) {
                uint32_t bo = (uint32_t)(c0w + tp * 16) * SA + b4row + kb;
                ldsm4(b_h[tp], st + P1_BH + bo);
                ldsm4(b_l[tp], st + P1_BL + bo);
            }
            ldsm4(bc, st + cmb_base + kb);
#pragma unroll
            for (int mt = 0; mt < 2; mt++) {
#pragma unroll
                for (int tp = 0; tp < 2; tp++) {
                    mma_bf16(acc[mt][2 * tp],     a_h[mt], b_h[tp][0], b_h[tp][1]);
                    mma_bf16(acc[mt][2 * tp],     a_h[mt], b_l[tp][0], b_l[tp][1]);
                    mma_bf16(acc[mt][2 * tp],     a_l[mt], b_h[tp][0], b_h[tp][1]);
                    mma_bf16(acc[mt][2 * tp + 1], a_h[mt], b_h[tp][2], b_h[tp][3]);
                    mma_bf16(acc[mt][2 * tp + 1], a_h[mt], b_l[tp][2], b_l[tp][3]);
                    mma_bf16(acc[mt][2 * tp + 1], a_l[mt], b_h[tp][2], b_h[tp][3]);
                }
                mma_bf16(acc[mt][4], a_h[mt], bc[0], bc[1]);
                mma_bf16(acc[mt][4], a_h[mt], bc[2], bc[3]);
                mma_bf16(acc[mt][4], a_l[mt], bc[0], bc[1]);
            }
        }
        if (it < 15) store_A(s ^ 1, pf);
        __syncthreads();
    }

    float* myscr = (float*)(smem + (kh1 ? SCR1_OFF : SCR0_OFF));
#pragma unroll
    for (int mt = 0; mt < 2; mt++) {
        const int row0 = r01 + mt * 16 + g;
#pragma unroll
        for (int t = 0; t < 5; t++) {
            const int col = c0w + t * 8 + 2 * q;
            myscr[row0 * SCR_S + col]       = acc[mt][t][0];
            myscr[row0 * SCR_S + col + 1]   = acc[mt][t][1];
            myscr[(row0 + 8) * SCR_S + col]     = acc[mt][t][2];
            myscr[(row0 + 8) * SCR_S + col + 1] = acc[mt][t][3];
        }
    }
    __syncthreads();

    auto load_W = [&](int oc, uint32_t ws) {
        const int k0 = oc * 128;
        for (int i = tid; i < 1280; i += 256) {
            int r = i >> 4, c = i & 15;
            uint32_t off = (uint32_t)r * W_PITCH + (uint32_t)c * 16;
            CP16(sb + ws + off, weh + (size_t)r * HW2 + k0 + c * 8);
            CP16(sb + ws + W_HL + off, wel + (size_t)r * HW2 + k0 + c * 8);
        }
    };
    load_W(0, WS_A);
    CP_COMMIT();

    uint32_t* atth = (uint32_t*)(smem + ATTH_OFF);
    uint32_t* attl = (uint32_t*)(smem + ATTL_OFF);
    {
        const int row = tid >> 2, t4 = tid & 3;
        float* r0p = (float*)(smem + SCR0_OFF) + row * SCR_S;
        float* r1p = (float*)(smem + SCR1_OFF) + row * SCR_S;
        float vals[20];
        const int n0 = t4 * 20;
        const int n1 = (n0 + 20 < NW) ? n0 + 20 : NW;
        float mx = -1e30f;
        for (int n = n0; n < n1; n++) {
            float v = r0p[n] + r1p[n];
            vals[n - n0] = v;
            mx = fmaxf(mx, v);
        }
        mx = fmaxf(mx, __shfl_xor_sync(0xffffffffu, mx, 1));
        mx = fmaxf(mx, __shfl_xor_sync(0xffffffffu, mx, 2));
        float s = 0.f;
        for (int n = n0; n < n1; n++) {
            float e = __expf(vals[n - n0] - mx);
            vals[n - n0] = e;
            s += e;
        }
        s += __shfl_xor_sync(0xffffffffu, s, 1);
        s += __shfl_xor_sync(0xffffffffu, s, 2);
        const float inv = 1.f / s;
#pragma unroll
        for (int p = 0; p < 10; p++) {
            const int pp = t4 * 10 + p;
            float v0 = (2 * pp < n1 && 2 * pp >= n0)         ? vals[2 * pp - n0] * inv     : 0.f;
            float v1 = (2 * pp + 1 < n1 && 2 * pp + 1 >= n0) ? vals[2 * pp + 1 - n0] * inv : 0.f;
            uint32_t ph, pl;
            split2(v0, v1, ph, pl);
            atth[row * ATT_S + pp] = ph;
            attl[row * ATT_S + pp] = pl;
        }
    }
    __syncthreads();

    const int rg3 = wid & 1;
    const int cg3 = wid >> 1;
    const int r03 = rg3 * 32;
    const int c0w3 = cg3 * 32;

    for (int oc = 0; oc < 8; oc++) {
        const uint32_t ws = (oc & 1) ? WS_B : WS_A;
        if (oc < 7) { load_W(oc + 1, (oc & 1) ? WS_A : WS_B); CP_COMMIT(); }
        if (oc < 7) CP_WAIT1(); else CP_WAIT0();
        __syncthreads();

        float acc2[2][4][4];
#pragma unroll
        for (int mt = 0; mt < 2; mt++)
#pragma unroll
            for (int t = 0; t < 4; t++)
#pragma unroll
                for (int j = 0; j < 4; j++) acc2[mt][t][j] = 0.f;

#pragma unroll
        for (int ks = 0; ks < 5; ks++) {
            uint32_t a_h[2][4], a_l[2][4];
#pragma unroll
            for (int mt = 0; mt < 2; mt++) {
                uint32_t aoff = ((uint32_t)(r03 + mt * 16 + ar + lb3 * 8) * ATT_S +
                                 (uint32_t)(ks * 8 + lb4 * 4)) * 4;
                ldsm4(a_h[mt], sb + ATTH_OFF + aoff);
                ldsm4(a_l[mt], sb + ATTL_OFF + aoff);
            }
#pragma unroll
            for (int tp = 0; tp < 2; tp++) {
                uint32_t woff = (uint32_t)(ks * 16 + ar + lb3 * 8) * W_PITCH +
                                (uint32_t)(c0w3 + tp * 16 + lb4 * 8) * 2;
                uint32_t b_h[4], b_l[4];
                ldsm4t(b_h, sb + ws + woff);
                ldsm4t(b_l, sb + ws + W_HL + woff);
#pragma unroll
                for (int mt = 0; mt < 2; mt++) {
                    mma_bf16(acc2[mt][2 * tp],     a_h[mt], b_h[0], b_h[1]);
                    mma_bf16(acc2[mt][2 * tp],     a_h[mt], b_l[0], b_l[1]);
                    mma_bf16(acc2[mt][2 * tp],     a_l[mt], b_h[0], b_h[1]);
                    mma_bf16(acc2[mt][2 * tp + 1], a_h[mt], b_h[2], b_h[3]);
                    mma_bf16(acc2[mt][2 * tp + 1], a_h[mt], b_l[2], b_l[3]);
                    mma_bf16(acc2[mt][2 * tp + 1], a_l[mt], b_h[2], b_h[3]);
                }
            }
        }

        const int k0 = oc * 128;
#pragma unroll
        for (int mt = 0; mt < 2; mt++) {
            float* ob = out + ((size_t)b * CC + c0 + r03 + mt * 16) * HW2 + k0 + c0w3;
#pragma unroll
            for (int t = 0; t < 4; t++) {
                int col = t * 8 + 2 * q;
                *(float2*)&ob[(size_t)g * HW2 + col]       = make_float2(acc2[mt][t][0], acc2[mt][t][1]);
                *(float2*)&ob[(size_t)(g + 8) * HW2 + col] = make_float2(acc2[mt][t][2], acc2[mt][t][3]);
            }
        }
        __syncthreads();
    }
}

// ---------------------------------------------------------------------------
extern "C" void kernel_launch(void* const* d_in, const int* in_sizes, int n_in,
                              void* d_out, int out_size) {
    const float* feat     = (const float*)d_in[0];
    const float* word_emb = (const float*)d_in[1];
    const float* W_fc     = (const float*)d_in[2];
    const float* b_fc     = (const float*)d_in[3];
    float* out            = (float*)d_out;
    (void)in_sizes; (void)n_in; (void)out_size;

    cudaFuncSetAttribute(we_gemm_tc, cudaFuncAttributeMaxDynamicSharedMemorySize, G_SMEM);
    cudaFuncSetAttribute(attn_tc, cudaFuncAttributeMaxDynamicSharedMemorySize, SMEM_ATT);

    split_inputs<<<(A_TASKS + W_TASKS + 255) / 256, 256>>>(word_emb, W_fc);
    we_gemm_tc<<<dim3(HW2 / 128, MP / 64), 256, G_SMEM>>>(b_fc);    // (8, 40)
    attn_tc<<<dim3(CC / 64, BB), 256, SMEM_ATT>>>(feat, out);       // (8, 32)
}

// round 17
// speedup vs baseline: 1.2006x; 1.0232x over previous
#include <cuda_runtime.h>
#include <cuda_bf16.h>
#include <cstdint>

#define BB   32
#define CC   512
#define HW2  1024
#define NW   77
#define NP   80          // padded n
#define WD   256
#define MP   (BB * NP)   // 2560 padded rows

// ---------------- scratch ----------------
__device__ __nv_bfloat16 g_a_hi[(size_t)MP * WD];
__device__ __nv_bfloat16 g_a_lo[(size_t)MP * WD];
__device__ __nv_bfloat16 g_w_hi[(size_t)HW2 * WD];
__device__ __nv_bfloat16 g_w_lo[(size_t)HW2 * WD];
__device__ __nv_bfloat16 g_we_hi[(size_t)BB * NP * HW2];
__device__ __nv_bfloat16 g_we_lo[(size_t)BB * NP * HW2];

// ---------------- helpers ----------------
__device__ __forceinline__ uint32_t smem_to_u32(const void* p) {
    uint32_t a;
    asm("{ .reg .u64 t; cvta.to.shared.u64 t, %1; cvt.u32.u64 %0, t; }" : "=r"(a) : "l"(p));
    return a;
}
__device__ __forceinline__ void mma_bf16(float* c, const uint32_t* a, uint32_t b0, uint32_t b1) {
    asm volatile(
        "mma.sync.aligned.m16n8k16.row.col.f32.bf16.bf16.f32 "
        "{%0,%1,%2,%3}, {%4,%5,%6,%7}, {%8,%9}, {%0,%1,%2,%3};"
        : "+f"(c[0]), "+f"(c[1]), "+f"(c[2]), "+f"(c[3])
        : "r"(a[0]), "r"(a[1]), "r"(a[2]), "r"(a[3]), "r"(b0), "r"(b1));
}
__device__ __forceinline__ void ldsm4(uint32_t* r, uint32_t addr) {
    asm volatile("ldmatrix.sync.aligned.m8n8.x4.shared.b16 {%0,%1,%2,%3}, [%4];"
        : "=r"(r[0]), "=r"(r[1]), "=r"(r[2]), "=r"(r[3]) : "r"(addr));
}
__device__ __forceinline__ void ldsm4t(uint32_t* r, uint32_t addr) {
    asm volatile("ldmatrix.sync.aligned.m8n8.x4.trans.shared.b16 {%0,%1,%2,%3}, [%4];"
        : "=r"(r[0]), "=r"(r[1]), "=r"(r[2]), "=r"(r[3]) : "r"(addr));
}
// Fast 2-way bf16 hi/lo split: hi = truncated upper 16 bits (exact residual),
// hi-pair packed with one PRMT, lo-pair with one cvt.rn.bf16x2.
__device__ __forceinline__ void split2(float v0, float v1, uint32_t& ph, uint32_t& pl) {
    uint32_t u0 = __float_as_uint(v0), u1 = __float_as_uint(v1);
    ph = __byte_perm(u0, u1, 0x7632);
    float r0 = v0 - __uint_as_float(u0 & 0xffff0000u);
    float r1 = v1 - __uint_as_float(u1 & 0xffff0000u);
    asm("cvt.rn.bf16x2.f32 %0, %1, %2;" : "=r"(pl) : "f"(r1), "f"(r0));
}
#define CP16(dst, src) asm volatile("cp.async.cg.shared.global [%0], [%1], 16;" :: "r"(dst), "l"(src))
#define CP_COMMIT()    asm volatile("cp.async.commit_group;" ::: "memory")
#define CP_WAIT0()     asm volatile("cp.async.wait_group 0;" ::: "memory")
#define CP_WAIT1()     asm volatile("cp.async.wait_group 1;" ::: "memory")

#define SA  144

// ---------------------------------------------------------------------------
// Kernel 0: elementwise bf16 hi/lo split of word_emb (padded) + W_fc
// ---------------------------------------------------------------------------
#define A_TASKS (MP * WD / 4)
#define W_TASKS (HW2 * WD / 4)
__global__ void split_inputs(const float* __restrict__ we_in,
                             const float* __restrict__ Wfc) {
    int idx = blockIdx.x * 256 + threadIdx.x;
    if (idx < A_TASKS) {
        int mp = idx >> 6, c4 = idx & 63;
        int bb = mp / NP, nn = mp % NP;
        float4 v = make_float4(0.f, 0.f, 0.f, 0.f);
        if (nn < NW) v = *(const float4*)(we_in + ((size_t)bb * NW + nn) * WD + c4 * 4);
        uint32_t h0, l0, h1, l1;
        split2(v.x, v.y, h0, l0);
        split2(v.z, v.w, h1, l1);
        *(uint2*)(g_a_hi + (size_t)mp * WD + c4 * 4) = make_uint2(h0, h1);
        *(uint2*)(g_a_lo + (size_t)mp * WD + c4 * 4) = make_uint2(l0, l1);
    } else if (idx < A_TASKS + W_TASKS) {
        int j = idx - A_TASKS;
        int r = j >> 6, c4 = j & 63;
        float4 v = *(const float4*)(Wfc + (size_t)r * WD + c4 * 4);
        uint32_t h0, l0, h1, l1;
        split2(v.x, v.y, h0, l0);
        split2(v.z, v.w, h1, l1);
        *(uint2*)(g_w_hi + (size_t)r * WD + c4 * 4) = make_uint2(h0, h1);
        *(uint2*)(g_w_lo + (size_t)r * WD + c4 * 4) = make_uint2(l0, l1);
    }
}

// ---------------------------------------------------------------------------
// Kernel 1: we = word_emb @ W_fc^T + b_fc (bf16 GEMM, cp.async 2-stage,
// single-sync pipeline). 64-row CTAs, 8 warps = 2rg(32r) x 4cg(32c).
// ---------------------------------------------------------------------------
#define G_AH 0
#define G_AL 9216
#define G_BH 18432
#define G_BL 36864
#define G_STAGE 55296
#define G_SMEM  110592

__global__ __launch_bounds__(256, 2) void we_gemm_tc(const float* __restrict__ bfc) {
    extern __shared__ char smem[];
    const uint32_t sb = smem_to_u32(smem);
    const int tid  = threadIdx.x;
    const int wid  = tid >> 5;
    const int lane = tid & 31;
    const int q    = lane & 3;
    const int g    = lane >> 2;
    const int rg   = wid & 1;
    const int cg   = wid >> 1;
    const int m0   = blockIdx.y * 64;
    const int k0   = blockIdx.x * 128;
    const int r0   = rg * 32;
    const int c0w  = cg * 32;

    float acc[2][4][4];
#pragma unroll
    for (int mt = 0; mt < 2; mt++)
#pragma unroll
        for (int t = 0; t < 4; t++)
#pragma unroll
            for (int j = 0; j < 4; j++) acc[mt][t][j] = 0.f;

    const int am = lane >> 3;
    const int ar = lane & 7;
    const uint32_t arow = (uint32_t)((am & 1) * 8 + ar) * SA + (uint32_t)(am >> 1) * 16;
    const uint32_t b4row = (uint32_t)((lane >> 4) * 8 + ar) * SA + (uint32_t)((lane >> 3) & 1) * 16;

    auto load_chunk = [&](int ch, int s) {
        const int kc = ch * 64;
        const uint32_t st = sb + (uint32_t)s * G_STAGE;
        for (int i = tid; i < 1024; i += 256) {
            int r = i >> 3, c = i & 7;
            uint32_t off = (uint32_t)r * SA + (uint32_t)c * 16;
            CP16(st + G_BH + off, g_w_hi + (size_t)(k0 + r) * WD + kc + c * 8);
            CP16(st + G_BL + off, g_w_lo + (size_t)(k0 + r) * WD + kc + c * 8);
            if (r < 64) {
                CP16(st + G_AH + off, g_a_hi + (size_t)(m0 + r) * WD + kc + c * 8);
                CP16(st + G_AL + off, g_a_lo + (size_t)(m0 + r) * WD + kc + c * 8);
            }
        }
    };

    load_chunk(0, 0);
    CP_COMMIT();

    for (int ch = 0; ch < 4; ch++) {
        const int s = ch & 1;
        __syncthreads();
        if (ch < 3) { load_chunk(ch + 1, s ^ 1); CP_COMMIT(); }
        if (ch < 3) CP_WAIT1(); else CP_WAIT0();
        __syncthreads();

        const uint32_t st = sb + (uint32_t)s * G_STAGE;
#pragma unroll
        for (int ks = 0; ks < 4; ks++) {
            const uint32_t kb = (uint32_t)ks * 32;
            uint32_t a_h[2][4], a_l[2][4];
#pragma unroll
            for (int mt = 0; mt < 2; mt++) {
                uint32_t ao = (uint32_t)(r0 + mt * 16) * SA + arow + kb;
                ldsm4(a_h[mt], st + G_AH + ao);
                ldsm4(a_l[mt], st + G_AL + ao);
            }
#pragma unroll
            for (int tp = 0; tp < 2; tp++) {
                uint32_t bo = (uint32_t)(c0w + tp * 16) * SA + b4row + kb;
                uint32_t b_h[4], b_l[4];
                ldsm4(b_h, st + G_BH + bo);
                ldsm4(b_l, st + G_BL + bo);
#pragma unroll
                for (int mt = 0; mt < 2; mt++) {
                    mma_bf16(acc[mt][2 * tp],     a_h[mt], b_h[0], b_h[1]);
                    mma_bf16(acc[mt][2 * tp],     a_h[mt], b_l[0], b_l[1]);
                    mma_bf16(acc[mt][2 * tp],     a_l[mt], b_h[0], b_h[1]);
                    mma_bf16(acc[mt][2 * tp + 1], a_h[mt], b_h[2], b_h[3]);
                    mma_bf16(acc[mt][2 * tp + 1], a_h[mt], b_l[2], b_l[3]);
                    mma_bf16(acc[mt][2 * tp + 1], a_l[mt], b_h[2], b_h[3]);
                }
            }
        }
    }

    // epilogue
#pragma unroll
    for (int mt = 0; mt < 2; mt++) {
        const int mp0 = m0 + r0 + mt * 16 + g;
        const int mp1 = mp0 + 8;
        const bool v0ok = ((mp0 % NP) < NW);
        const bool v1ok = ((mp1 % NP) < NW);
#pragma unroll
        for (int t = 0; t < 4; t++) {
            const int col = k0 + c0w + t * 8 + 2 * q;
            const float b0 = bfc[col], b1 = bfc[col + 1];
            float v00 = v0ok ? acc[mt][t][0] + b0 : 0.f;
            float v01 = v0ok ? acc[mt][t][1] + b1 : 0.f;
            float v10 = v1ok ? acc[mt][t][2] + b0 : 0.f;
            float v11 = v1ok ? acc[mt][t][3] + b1 : 0.f;
            uint32_t ph, pl;
            split2(v00, v01, ph, pl);
            *(uint32_t*)(g_we_hi + (size_t)mp0 * HW2 + col) = ph;
            *(uint32_t*)(g_we_lo + (size_t)mp0 * HW2 + col) = pl;
            split2(v10, v11, ph, pl);
            *(uint32_t*)(g_we_hi + (size_t)mp1 * HW2 + col) = ph;
            *(uint32_t*)(g_we_lo + (size_t)mp1 * HW2 + col) = pl;
        }
    }
}

// ---------------------------------------------------------------------------
// Kernel 2: fused attention (R14 structure, single-sync pipelines)
// ---------------------------------------------------------------------------
#define P1_AH 0
#define P1_AL 9216
#define P1_BH 18432
#define P1_BL 29952
#define P1_STAGE 41472
#define SCR0_OFF 0
#define SCR1_OFF 20736
#define SCR_S    81
#define WS_A     43520
#define WS_B     0
#define W_PITCH  272
#define W_HL     21760
#define ATTH_OFF 87040
#define ATTL_OFF 98304
#define ATT_S    44
#define SMEM_ATT 109568

__global__ __launch_bounds__(256, 2) void attn_tc(const float* __restrict__ feat,
                                                  float* __restrict__ out) {
    extern __shared__ char smem[];
    const uint32_t sb = smem_to_u32(smem);
    const int tid  = threadIdx.x;
    const int wid  = tid >> 5;
    const int lane = tid & 31;
    const int q    = lane & 3;
    const int g    = lane >> 2;
    const int b    = blockIdx.y;
    const int c0   = blockIdx.x * 64;

    const int rg1 = wid & 1;
    const int cg1 = (wid >> 1) & 1;
    const int kh1 = wid >> 2;
    const int r01 = rg1 * 32;
    const int c0w = cg1 * 40;

    const float* fb = feat + ((size_t)b * CC + c0) * HW2;
    const __nv_bfloat16* weh = g_we_hi + (size_t)b * NP * HW2;
    const __nv_bfloat16* wel = g_we_lo + (size_t)b * NP * HW2;

    const int ar = lane & 7;
    const int lb3 = (lane >> 3) & 1;
    const int lb4 = lane >> 4;
    const int am = lane >> 3;
    const uint32_t arow = (uint32_t)((am & 1) * 8 + ar) * SA + (uint32_t)(am >> 1) * 16;
    const uint32_t b4row = (uint32_t)(lb4 * 8 + ar) * SA + (uint32_t)lb3 * 16;
    const uint32_t cmb_base = (uint32_t)((lane < 16) ? P1_BH : P1_BL) +
                              (uint32_t)(c0w + 32 + ar) * SA +
                              (uint32_t)lb3 * 16;

    const int lr = tid >> 2, lh = tid & 3;
    auto load_A_regs = [&](int ch, float4* pf) {
        const float* src = fb + (size_t)lr * HW2 + ch * 64 + lh * 16;
#pragma unroll
        for (int i = 0; i < 4; i++) pf[i] = *(const float4*)(src + i * 4);
    };
    auto store_A = [&](int s, const float4* pf) {
        uint32_t h[8], l[8];
#pragma unroll
        for (int i = 0; i < 4; i++) {
            split2(pf[i].x, pf[i].y, h[2 * i], l[2 * i]);
            split2(pf[i].z, pf[i].w, h[2 * i + 1], l[2 * i + 1]);
        }
        uint4* ph_ = (uint4*)(smem + s * P1_STAGE + P1_AH + lr * SA + lh * 32);
        uint4* pl_ = (uint4*)(smem + s * P1_STAGE + P1_AL + lr * SA + lh * 32);
        ph_[0] = make_uint4(h[0], h[1], h[2], h[3]);
        ph_[1] = make_uint4(h[4], h[5], h[6], h[7]);
        pl_[0] = make_uint4(l[0], l[1], l[2], l[3]);
        pl_[1] = make_uint4(l[4], l[5], l[6], l[7]);
    };
    auto load_B = [&](int ch, int s) {
        const int kc = ch * 64;
        const uint32_t st = sb + (uint32_t)s * P1_STAGE;
        for (int i = tid; i < 640; i += 256) {
            int r = i >> 3, cch = i & 7;
            uint32_t off = (uint32_t)r * SA + (uint32_t)cch * 16;
            CP16(st + P1_BH + off, weh + (size_t)r * HW2 + kc + cch * 8);
            CP16(st + P1_BL + off, wel + (size_t)r * HW2 + kc + cch * 8);
        }
    };

    // ================= Phase 1: partial scores (single-sync pipeline) ========
    float acc[2][5][4];
#pragma unroll
    for (int mt = 0; mt < 2; mt++)
#pragma unroll
        for (int t = 0; t < 5; t++)
#pragma unroll
            for (int j = 0; j < 4; j++) acc[mt][t][j] = 0.f;

    float4 pf[4];
    load_A_regs(0, pf);
    load_B(0, 0);
    CP_COMMIT();
    store_A(0, pf);
    load_A_regs(1, pf);

    for (int it = 0; it < 16; it++) {
        const int s = it & 1;
        __syncthreads();                 // all warps done reading stage s^1 (iter it-1)
        if (it < 15) {
            load_B(it + 1, s ^ 1);
            CP_COMMIT();
            store_A(s ^ 1, pf);          // pf holds A(it+1)
        }
        if (it < 14) load_A_regs(it + 2, pf);
        if (it < 15) CP_WAIT1(); else CP_WAIT0();

        const uint32_t st = sb + (uint32_t)s * P1_STAGE;
#pragma unroll
        for (int ks = 0; ks < 2; ks++) {
            const uint32_t kb = (uint32_t)(kh1 * 64 + ks * 32);
            uint32_t a_h[2][4], a_l[2][4];
#pragma unroll
            for (int mt = 0; mt < 2; mt++) {
                uint32_t ao = (uint32_t)(r01 + mt * 16) * SA + arow + kb;
                ldsm4(a_h[mt], st + P1_AH + ao);
                ldsm4(a_l[mt], st + P1_AL + ao);
            }
            uint32_t b_h[2][4], b_l[2][4], bc[4];
#pragma unroll
            for (int tp = 0; tp < 2; tp++) {
                uint32_t bo = (uint32_t)(c0w + tp * 16) * SA + b4row + kb;
                ldsm4(b_h[tp], st + P1_BH + bo);
                ldsm4(b_l[tp], st + P1_BL + bo);
            }
            ldsm4(bc, st + cmb_base + kb);
#pragma unroll
            for (int mt = 0; mt < 2; mt++) {
#pragma unroll
                for (int tp = 0; tp < 2; tp++) {
                    mma_bf16(acc[mt][2 * tp],     a_h[mt], b_h[tp][0], b_h[tp][1]);
                    mma_bf16(acc[mt][2 * tp],     a_h[mt], b_l[tp][0], b_l[tp][1]);
                    mma_bf16(acc[mt][2 * tp],     a_l[mt], b_h[tp][0], b_h[tp][1]);
                    mma_bf16(acc[mt][2 * tp + 1], a_h[mt], b_h[tp][2], b_h[tp][3]);
                    mma_bf16(acc[mt][2 * tp + 1], a_h[mt], b_l[tp][2], b_l[tp][3]);
                    mma_bf16(acc[mt][2 * tp + 1], a_l[mt], b_h[tp][2], b_h[tp][3]);
                }
                mma_bf16(acc[mt][4], a_h[mt], bc[0], bc[1]);
                mma_bf16(acc[mt][4], a_h[mt], bc[2], bc[3]);
                mma_bf16(acc[mt][4], a_l[mt], bc[0], bc[1]);
            }
        }
    }
    __syncthreads();                     // phase-1 reads done before score writes reuse space

    float* myscr = (float*)(smem + (kh1 ? SCR1_OFF : SCR0_OFF));
#pragma unroll
    for (int mt = 0; mt < 2; mt++) {
        const int row0 = r01 + mt * 16 + g;
#pragma unroll
        for (int t = 0; t < 5; t++) {
            const int col = c0w + t * 8 + 2 * q;
            myscr[row0 * SCR_S + col]       = acc[mt][t][0];
            myscr[row0 * SCR_S + col + 1]   = acc[mt][t][1];
            myscr[(row0 + 8) * SCR_S + col]     = acc[mt][t][2];
            myscr[(row0 + 8) * SCR_S + col + 1] = acc[mt][t][3];
        }
    }
    __syncthreads();

    // ================= Phase 2: prefetch W0 + softmax =================
    auto load_W = [&](int oc, uint32_t ws) {
        const int k0 = oc * 128;
        for (int i = tid; i < 1280; i += 256) {
            int r = i >> 4, c = i & 15;
            uint32_t off = (uint32_t)r * W_PITCH + (uint32_t)c * 16;
            CP16(sb + ws + off, weh + (size_t)r * HW2 + k0 + c * 8);
            CP16(sb + ws + W_HL + off, wel + (size_t)r * HW2 + k0 + c * 8);
        }
    };
    load_W(0, WS_A);
    CP_COMMIT();

    uint32_t* atth = (uint32_t*)(smem + ATTH_OFF);
    uint32_t* attl = (uint32_t*)(smem + ATTL_OFF);
    {
        const int row = tid >> 2, t4 = tid & 3;
        float* r0p = (float*)(smem + SCR0_OFF) + row * SCR_S;
        float* r1p = (float*)(smem + SCR1_OFF) + row * SCR_S;
        float vals[20];
        const int n0 = t4 * 20;
        const int n1 = (n0 + 20 < NW) ? n0 + 20 : NW;
        float mx = -1e30f;
        for (int n = n0; n < n1; n++) {
            float v = r0p[n] + r1p[n];
            vals[n - n0] = v;
            mx = fmaxf(mx, v);
        }
        mx = fmaxf(mx, __shfl_xor_sync(0xffffffffu, mx, 1));
        mx = fmaxf(mx, __shfl_xor_sync(0xffffffffu, mx, 2));
        float s = 0.f;
        for (int n = n0; n < n1; n++) {
            float e = __expf(vals[n - n0] - mx);
            vals[n - n0] = e;
            s += e;
        }
        s += __shfl_xor_sync(0xffffffffu, s, 1);
        s += __shfl_xor_sync(0xffffffffu, s, 2);
        const float inv = 1.f / s;
#pragma unroll
        for (int p = 0; p < 10; p++) {
            const int pp = t4 * 10 + p;
            float v0 = (2 * pp < n1 && 2 * pp >= n0)         ? vals[2 * pp - n0] * inv     : 0.f;
            float v1 = (2 * pp + 1 < n1 && 2 * pp + 1 >= n0) ? vals[2 * pp + 1 - n0] * inv : 0.f;
            uint32_t ph, pl;
            split2(v0, v1, ph, pl);
            atth[row * ATT_S + pp] = ph;
            attl[row * ATT_S + pp] = pl;
        }
    }

    // ================= Phase 3: out = att @ we (single-sync pipeline) ========
    const int rg3 = wid & 1;
    const int cg3 = wid >> 1;
    const int r03 = rg3 * 32;
    const int c0w3 = cg3 * 32;

    for (int oc = 0; oc < 8; oc++) {
        const uint32_t ws = (oc & 1) ? WS_B : WS_A;
        __syncthreads();                 // all warps done with stage being overwritten
        if (oc < 7) { load_W(oc + 1, (oc & 1) ? WS_A : WS_B); CP_COMMIT(); }
        if (oc < 7) CP_WAIT1(); else CP_WAIT0();

        float acc2[2][4][4];
#pragma unroll
        for (int mt = 0; mt < 2; mt++)
#pragma unroll
            for (int t = 0; t < 4; t++)
#pragma unroll
                for (int j = 0; j < 4; j++) acc2[mt][t][j] = 0.f;

#pragma unroll
        for (int ks = 0; ks < 5; ks++) {
            uint32_t a_h[2][4], a_l[2][4];
#pragma unroll
            for (int mt = 0; mt < 2; mt++) {
                uint32_t aoff = ((uint32_t)(r03 + mt * 16 + ar + lb3 * 8) * ATT_S +
                                 (uint32_t)(ks * 8 + lb4 * 4)) * 4;
                ldsm4(a_h[mt], sb + ATTH_OFF + aoff);
                ldsm4(a_l[mt], sb + ATTL_OFF + aoff);
            }
#pragma unroll
            for (int tp = 0; tp < 2; tp++) {
                uint32_t woff = (uint32_t)(ks * 16 + ar + lb3 * 8) * W_PITCH +
                                (uint32_t)(c0w3 + tp * 16 + lb4 * 8) * 2;
                uint32_t b_h[4], b_l[4];
                ldsm4t(b_h, sb + ws + woff);
                ldsm4t(b_l, sb + ws + W_HL + woff);
#pragma unroll
                for (int mt = 0; mt < 2; mt++) {
                    mma_bf16(acc2[mt][2 * tp],     a_h[mt], b_h[0], b_h[1]);
                    mma_bf16(acc2[mt][2 * tp],     a_h[mt], b_l[0], b_l[1]);
                    mma_bf16(acc2[mt][2 * tp],     a_l[mt], b_h[0], b_h[1]);
                    mma_bf16(acc2[mt][2 * tp + 1], a_h[mt], b_h[2], b_h[3]);
                    mma_bf16(acc2[mt][2 * tp + 1], a_h[mt], b_l[2], b_l[3]);
                    mma_bf16(acc2[mt][2 * tp + 1], a_l[mt], b_h[2], b_h[3]);
                }
            }
        }

        const int k0 = oc * 128;
#pragma unroll
        for (int mt = 0; mt < 2; mt++) {
            float* ob = out + ((size_t)b * CC + c0 + r03 + mt * 16) * HW2 + k0 + c0w3;
#pragma unroll
            for (int t = 0; t < 4; t++) {
                int col = t * 8 + 2 * q;
                *(float2*)&ob[(size_t)g * HW2 + col]       = make_float2(acc2[mt][t][0], acc2[mt][t][1]);
                *(float2*)&ob[(size_t)(g + 8) * HW2 + col] = make_float2(acc2[mt][t][2], acc2[mt][t][3]);
            }
        }
    }
}

// ---------------------------------------------------------------------------
extern "C" void kernel_launch(void* const* d_in, const int* in_sizes, int n_in,
                              void* d_out, int out_size) {
    const float* feat     = (const float*)d_in[0];
    const float* word_emb = (const float*)d_in[1];
    const float* W_fc     = (const float*)d_in[2];
    const float* b_fc     = (const float*)d_in[3];
    float* out            = (float*)d_out;
    (void)in_sizes; (void)n_in; (void)out_size;

    cudaFuncSetAttribute(we_gemm_tc, cudaFuncAttributeMaxDynamicSharedMemorySize, G_SMEM);
    cudaFuncSetAttribute(attn_tc, cudaFuncAttributeMaxDynamicSharedMemorySize, SMEM_ATT);

    split_inputs<<<(A_TASKS + W_TASKS + 255) / 256, 256>>>(word_emb, W_fc);
    we_gemm_tc<<<dim3(HW2 / 128, MP / 64), 256, G_SMEM>>>(b_fc);    // (8, 40)
    attn_tc<<<dim3(CC / 64, BB), 256, SMEM_ATT>>>(feat, out);       // (8, 32)
}